// round 1
// baseline (speedup 1.0000x reference)
#include <cuda_runtime.h>
#include <cstdint>
#include <cstddef>

// Problem constants (fixed by the reference):
//   E=16 experts, D=1024, H=4096, N=16384 tokens (1024 per expert, contiguous).
// GEMM1: per expert  [1024 x 4096 x 1024]  C = relu(X * W1^T + b1)
// GEMM2: per expert  [1024 x 1024 x 4096]  Y = Hid * W2^T + b2
// Both are "NT" GEMMs: A and B are K-major row-major.

static __device__ float g_hidden[(size_t)16384 * 4096];  // 256 MB scratch

__device__ __forceinline__ unsigned long long pack2(float lo, float hi) {
    unsigned long long r;
    asm("mov.b64 %0, {%1, %2};" : "=l"(r) : "f"(lo), "f"(hi));
    return r;
}
__device__ __forceinline__ void unpack2(unsigned long long v, float& lo, float& hi) {
    asm("mov.b64 {%0, %1}, %2;" : "=f"(lo), "=f"(hi) : "l"(v));
}
// Packed dual fp32 FMA: SASS FFMA2 (2x fp32 throughput vs 3-reg FFMA).
__device__ __forceinline__ void ffma2(unsigned long long& d,
                                      unsigned long long a,
                                      unsigned long long b) {
    asm("fma.rn.f32x2 %0, %1, %2, %3;" : "=l"(d) : "l"(a), "l"(b), "l"(d));
}

// Stage registers -> shared (transposed to [BK][M] so the compute loop reads
// contiguous along M/N). S = 132 padding to reduce STS bank conflicts.
#define STORE_STAGE(buf)                                                        \
    do {                                                                        \
        As[buf][lk + 0][lm]      = ra0.x;                                       \
        As[buf][lk + 1][lm]      = ra0.y;                                       \
        As[buf][lk + 2][lm]      = ra0.z;                                       \
        As[buf][lk + 3][lm]      = ra0.w;                                       \
        As[buf][lk + 0][lm + 64] = ra1.x;                                       \
        As[buf][lk + 1][lm + 64] = ra1.y;                                       \
        As[buf][lk + 2][lm + 64] = ra1.z;                                       \
        As[buf][lk + 3][lm + 64] = ra1.w;                                       \
        Bs[buf][lk + 0][lm]      = rb0.x;                                       \
        Bs[buf][lk + 1][lm]      = rb0.y;                                       \
        Bs[buf][lk + 2][lm]      = rb0.z;                                       \
        Bs[buf][lk + 3][lm]      = rb0.w;                                       \
        Bs[buf][lk + 0][lm + 64] = rb1.x;                                       \
        Bs[buf][lk + 1][lm + 64] = rb1.y;                                       \
        Bs[buf][lk + 2][lm + 64] = rb1.z;                                       \
        Bs[buf][lk + 3][lm + 64] = rb1.w;                                       \
    } while (0)

template <int NCOLS, int KDIM, bool RELU>
__global__ __launch_bounds__(256, 2)
void expert_gemm(const float* __restrict__ A,     // [E, 1024, KDIM]
                 const float* __restrict__ B,     // [E, NCOLS, KDIM]
                 const float* __restrict__ bias,  // [E, NCOLS]
                 float* __restrict__ C)           // [E, 1024, NCOLS]
{
    constexpr int BM = 128, BN = 128, BK = 16, S = 132;
    constexpr int MROWS = 1024;
    constexpr int NK = KDIM / BK;
    (void)BN;

    __shared__ float As[2][BK][S];
    __shared__ float Bs[2][BK][S];

    const int e  = blockIdx.z;
    const int m0 = blockIdx.y * BM;
    const int n0 = blockIdx.x * BN;

    const float* Ab = A + (size_t)e * MROWS * KDIM + (size_t)m0 * KDIM;
    const float* Bb = B + (size_t)e * NCOLS * KDIM + (size_t)n0 * KDIM;

    const int tid = threadIdx.x;
    const int tx  = tid & 15;   // N direction (8 cols each)
    const int ty  = tid >> 4;   // M direction (8 rows each)
    const int lm  = tid >> 2;   // load row 0..63 (and +64)
    const int lk  = (tid & 3) * 4;  // load k offset 0/4/8/12

    float4 ra0, ra1, rb0, rb1;

    // Prologue: load k-tile 0
    {
        const float* ap = Ab + (size_t)lm * KDIM + lk;
        const float* bp = Bb + (size_t)lm * KDIM + lk;
        ra0 = *(const float4*)(ap);
        ra1 = *(const float4*)(ap + (size_t)64 * KDIM);
        rb0 = *(const float4*)(bp);
        rb1 = *(const float4*)(bp + (size_t)64 * KDIM);
    }

    unsigned long long acc[8][4];
#pragma unroll
    for (int i = 0; i < 8; i++)
#pragma unroll
        for (int j = 0; j < 4; j++) acc[i][j] = 0ULL;  // {0.f, 0.f}

    STORE_STAGE(0);
    __syncthreads();

    for (int kt = 0; kt < NK; ++kt) {
        const int cur = kt & 1;

        if (kt + 1 < NK) {  // prefetch next k-tile into registers
            const float* ap = Ab + (size_t)lm * KDIM + (size_t)(kt + 1) * BK + lk;
            const float* bp = Bb + (size_t)lm * KDIM + (size_t)(kt + 1) * BK + lk;
            ra0 = *(const float4*)(ap);
            ra1 = *(const float4*)(ap + (size_t)64 * KDIM);
            rb0 = *(const float4*)(bp);
            rb1 = *(const float4*)(bp + (size_t)64 * KDIM);
        }

#pragma unroll
        for (int k = 0; k < BK; ++k) {
            float4 a03 = *(const float4*)&As[cur][k][ty * 8];
            float4 a47 = *(const float4*)&As[cur][k][ty * 8 + 4];
            ulonglong2 bb0 = *(const ulonglong2*)&Bs[cur][k][tx * 8];
            ulonglong2 bb1 = *(const ulonglong2*)&Bs[cur][k][tx * 8 + 4];
            unsigned long long bv[4] = {bb0.x, bb0.y, bb1.x, bb1.y};
            unsigned long long a2[8];
            a2[0] = pack2(a03.x, a03.x);
            a2[1] = pack2(a03.y, a03.y);
            a2[2] = pack2(a03.z, a03.z);
            a2[3] = pack2(a03.w, a03.w);
            a2[4] = pack2(a47.x, a47.x);
            a2[5] = pack2(a47.y, a47.y);
            a2[6] = pack2(a47.z, a47.z);
            a2[7] = pack2(a47.w, a47.w);
#pragma unroll
            for (int i = 0; i < 8; i++)
#pragma unroll
                for (int j = 0; j < 4; j++) ffma2(acc[i][j], a2[i], bv[j]);
        }

        if (kt + 1 < NK) {
            STORE_STAGE(cur ^ 1);
            __syncthreads();
        }
    }

    // Epilogue: bias (+ optional relu), vectorized stores
    float bvv[8];
    {
        const float* bp = bias + (size_t)e * NCOLS + n0 + tx * 8;
        float4 t0 = *(const float4*)(bp);
        float4 t1 = *(const float4*)(bp + 4);
        bvv[0] = t0.x; bvv[1] = t0.y; bvv[2] = t0.z; bvv[3] = t0.w;
        bvv[4] = t1.x; bvv[5] = t1.y; bvv[6] = t1.z; bvv[7] = t1.w;
    }
    float* Cb = C + (size_t)e * MROWS * NCOLS + (size_t)(m0 + ty * 8) * NCOLS + n0 + tx * 8;
#pragma unroll
    for (int i = 0; i < 8; i++) {
        float o[8];
#pragma unroll
        for (int j = 0; j < 4; j++) unpack2(acc[i][j], o[2 * j], o[2 * j + 1]);
#pragma unroll
        for (int c = 0; c < 8; c++) {
            o[c] += bvv[c];
            if (RELU) o[c] = fmaxf(o[c], 0.0f);
        }
        float4* cp = (float4*)(Cb + (size_t)i * NCOLS);
        cp[0] = make_float4(o[0], o[1], o[2], o[3]);
        cp[1] = make_float4(o[4], o[5], o[6], o[7]);
    }
}

extern "C" void kernel_launch(void* const* d_in, const int* in_sizes, int n_in,
                              void* d_out, int out_size) {
    (void)in_sizes; (void)n_in; (void)out_size;
    const float* xs = (const float*)d_in[0];
    // d_in[1] = fwd_expert_count (uniform N/E, unused)
    const float* w1 = (const float*)d_in[2];
    const float* b1 = (const float*)d_in[3];
    const float* w2 = (const float*)d_in[4];
    const float* b2 = (const float*)d_in[5];
    float* out = (float*)d_out;

    void* hptr = nullptr;
    cudaGetSymbolAddress(&hptr, g_hidden);
    float* hid = (float*)hptr;

    dim3 blk(256);
    // GEMM1: [E] x (1024 x 4096 x 1024), fused bias + relu -> g_hidden
    expert_gemm<4096, 1024, true><<<dim3(32, 8, 16), blk>>>(xs, w1, b1, hid);
    // GEMM2: [E] x (1024 x 1024 x 4096), fused bias -> out
    expert_gemm<1024, 4096, false><<<dim3(8, 8, 16), blk>>>(hid, w2, b2, out);
}

// round 3
// speedup vs baseline: 2.7091x; 2.7091x over previous
#include <cuda_runtime.h>
#include <cstdint>
#include <cstddef>

// E=16, D=1024, H=4096, N=16384 (1024 tokens/expert, contiguous).
// GEMM1: per-expert [1024 x 4096 x 1024], C = relu(X*W1^T + b1)
// GEMM2: per-expert [1024 x 1024 x 4096], Y = H*W2^T + b2
// fp32 in/out; internally bf16 hi/lo 3-pass (Ootomo) with mma.sync m16n8k16
// (sm_80-class PTX only -- this harness compiles PTX for base sm_103, so all
// tcgen05/TMEM instructions are unavailable).

static __device__ float g_hidden[(size_t)16384 * 4096];  // 256 MB scratch

__device__ __forceinline__ uint32_t smem_u32(const void* p) {
    uint32_t a;
    asm("{ .reg .u64 t; cvta.to.shared.u64 t, %1; cvt.u32.u64 %0, t; }"
        : "=r"(a) : "l"(p));
    return a;
}
#define SW128(x) ((x) ^ (((x) >> 3) & 0x70))

// pack2: lower half = bf16(a), upper half = bf16(b)
__device__ __forceinline__ uint32_t pack_bf2(float a, float b) {
    uint32_t r;
    asm("cvt.rn.bf16x2.f32 %0, %1, %2;" : "=r"(r) : "f"(b), "f"(a));
    return r;
}
// 8 fp32 -> 8 bf16 hi (16B) + 8 bf16 lo (16B)
__device__ __forceinline__ void split8(const float4& A, const float4& B,
                                       uint4& H, uint4& L) {
    float f[8] = {A.x, A.y, A.z, A.w, B.x, B.y, B.z, B.w};
    uint32_t h[4], l[4];
#pragma unroll
    for (int p = 0; p < 4; p++) {
        h[p] = pack_bf2(f[2 * p], f[2 * p + 1]);
        float e0 = __uint_as_float(h[p] << 16);
        float e1 = __uint_as_float(h[p] & 0xFFFF0000u);
        l[p] = pack_bf2(f[2 * p] - e0, f[2 * p + 1] - e1);
    }
    H = make_uint4(h[0], h[1], h[2], h[3]);
    L = make_uint4(l[0], l[1], l[2], l[3]);
}

__device__ __forceinline__ void ldsm4(uint32_t* r, uint32_t addr) {
    asm volatile("ldmatrix.sync.aligned.m8n8.x4.shared.b16 {%0,%1,%2,%3}, [%4];"
                 : "=r"(r[0]), "=r"(r[1]), "=r"(r[2]), "=r"(r[3]) : "r"(addr));
}
__device__ __forceinline__ void mma16816(float* c, const uint32_t* a,
                                         uint32_t b0, uint32_t b1) {
    asm volatile(
        "mma.sync.aligned.m16n8k16.row.col.f32.bf16.bf16.f32 "
        "{%0,%1,%2,%3}, {%4,%5,%6,%7}, {%8,%9}, {%0,%1,%2,%3};"
        : "+f"(c[0]), "+f"(c[1]), "+f"(c[2]), "+f"(c[3])
        : "r"(a[0]), "r"(a[1]), "r"(a[2]), "r"(a[3]), "r"(b0), "r"(b1));
}

// SMEM stage layout (bf16, rows of 64 elems = 128B, SW128 swizzled):
//   Ahi @ 0      (16 KB)   Alo @ 16384
//   Bhi @ 32768  (16 KB)   Blo @ 49152
static constexpr int STAGE = 65536;
static constexpr int SMEM_TOTAL = 2 * STAGE;  // 128 KB

__device__ __forceinline__ void stage_seg(char* buf, int base_off, int row,
                                          int chunkb, const float4& x,
                                          const float4& y) {
    uint4 H, L;
    split8(x, y, H, L);
    int sw = SW128(row * 128 + chunkb);
    *(uint4*)(buf + base_off + sw)          = H;
    *(uint4*)(buf + base_off + 16384 + sw)  = L;
}

template <int NCOLS, int KDIM, bool RELU>
__global__ __launch_bounds__(256, 1)
void ffn_mma(const float* __restrict__ A,     // [E*1024, KDIM]
             const float* __restrict__ B,     // [E, NCOLS, KDIM]
             const float* __restrict__ bias,  // [E, NCOLS]
             float* __restrict__ C)           // [E*1024, NCOLS]
{
    constexpr int NK = KDIM / 64;
    extern __shared__ char smem[];
    const uint32_t smb = smem_u32(smem);

    const int tid  = threadIdx.x;
    const int lane = tid & 31, warp = tid >> 5;
    const int wm = warp >> 2, wn = warp & 3;  // warp tile: 64(M) x 32(N)
    const int e  = blockIdx.z;
    const int m0 = blockIdx.y * 128, n0 = blockIdx.x * 128;

    const float* Ab = A + ((size_t)e * 1024 + m0) * KDIM;
    const float* Bb = B + ((size_t)e * NCOLS + n0) * KDIM;

    // staging geometry: seg s = tid + t*256; row = (tid>>3)+t*32, chunk = tid&7
    const int r0 = tid >> 3;
    const int c8 = tid & 7;  // chunk of 8 fp32 = 16B bf16

    // ldmatrix per-thread base offsets (within a stage buffer)
    const int xmask = (lane & 7) << 4;
    const int a_b0 = (wm * 64 + (lane & 15)) * 128 + ((lane >> 4) & 1) * 16;
    const int b_b0 = (wn * 32 + (lane & 7) + ((lane >> 4) & 1) * 8) * 128 +
                     ((lane >> 3) & 1) * 16;

    float acc[4][4][4];
#pragma unroll
    for (int i = 0; i < 4; i++)
#pragma unroll
        for (int j = 0; j < 4; j++)
#pragma unroll
            for (int q = 0; q < 4; q++) acc[i][j][q] = 0.f;

    // ---- prologue: stage 0 -> buffer 0 ----
#pragma unroll
    for (int t = 0; t < 4; t++) {
        int row = r0 + t * 32;
        const float* pA = Ab + (size_t)row * KDIM + c8 * 8;
        const float* pB = Bb + (size_t)row * KDIM + c8 * 8;
        stage_seg(smem, 0,     row, c8 * 16, *(const float4*)pA, *(const float4*)(pA + 4));
        stage_seg(smem, 32768, row, c8 * 16, *(const float4*)pB, *(const float4*)(pB + 4));
    }
    __syncthreads();

    // ---- main loop ----
    for (int kt = 0; kt < NK; ++kt) {
        float4 pa[4][2], pb[4][2];
        if (kt + 1 < NK) {  // prefetch next stage (fp32) into registers
            const float* An = Ab + (kt + 1) * 64;
            const float* Bn = Bb + (kt + 1) * 64;
#pragma unroll
            for (int t = 0; t < 4; t++) {
                int row = r0 + t * 32;
                const float* pA = An + (size_t)row * KDIM + c8 * 8;
                const float* pB = Bn + (size_t)row * KDIM + c8 * 8;
                pa[t][0] = *(const float4*)pA; pa[t][1] = *(const float4*)(pA + 4);
                pb[t][0] = *(const float4*)pB; pb[t][1] = *(const float4*)(pB + 4);
            }
        }

        const uint32_t sA = smb + (kt & 1) * STAGE;
#pragma unroll
        for (int k16 = 0; k16 < 4; k16++) {
            uint32_t ah[4][4], al[4][4], bh[2][4], bl[2][4];
#pragma unroll
            for (int mt = 0; mt < 4; mt++) {
                int off = (a_b0 + mt * 2048 + k16 * 32) ^ xmask;
                ldsm4(ah[mt], sA + off);
                ldsm4(al[mt], sA + 16384 + off);
            }
#pragma unroll
            for (int nt2 = 0; nt2 < 2; nt2++) {
                int off = (b_b0 + nt2 * 2048 + k16 * 32) ^ xmask;
                ldsm4(bh[nt2], sA + 32768 + off);
                ldsm4(bl[nt2], sA + 49152 + off);
            }
#pragma unroll
            for (int mt = 0; mt < 4; mt++)
#pragma unroll
                for (int nt = 0; nt < 4; nt++) {
                    const int g = nt >> 1, s2 = (nt & 1) * 2;
                    mma16816(acc[mt][nt], ah[mt], bh[g][s2], bh[g][s2 + 1]);
                    mma16816(acc[mt][nt], ah[mt], bl[g][s2], bl[g][s2 + 1]);
                    mma16816(acc[mt][nt], al[mt], bh[g][s2], bh[g][s2 + 1]);
                }
        }

        if (kt + 1 < NK) {
            char* buf = smem + ((kt + 1) & 1) * STAGE;
#pragma unroll
            for (int t = 0; t < 4; t++) {
                int row = r0 + t * 32;
                stage_seg(buf, 0,     row, c8 * 16, pa[t][0], pa[t][1]);
                stage_seg(buf, 32768, row, c8 * 16, pb[t][0], pb[t][1]);
            }
        }
        __syncthreads();
    }

    // ---- epilogue: bias (+relu), direct STG.64 ----
    const float* bp = bias + (size_t)e * NCOLS + n0 + wn * 32;
    float2 bvv[4];
#pragma unroll
    for (int nt = 0; nt < 4; nt++)
        bvv[nt] = *(const float2*)(bp + nt * 8 + (lane & 3) * 2);

    float* Crow = C + ((size_t)e * 1024 + m0 + wm * 64) * NCOLS + n0 + wn * 32;
#pragma unroll
    for (int mt = 0; mt < 4; mt++) {
        int r = mt * 16 + (lane >> 2);
#pragma unroll
        for (int nt = 0; nt < 4; nt++) {
            int col = nt * 8 + (lane & 3) * 2;
            float2 v0, v1;
            v0.x = acc[mt][nt][0] + bvv[nt].x;
            v0.y = acc[mt][nt][1] + bvv[nt].y;
            v1.x = acc[mt][nt][2] + bvv[nt].x;
            v1.y = acc[mt][nt][3] + bvv[nt].y;
            if (RELU) {
                v0.x = fmaxf(v0.x, 0.f); v0.y = fmaxf(v0.y, 0.f);
                v1.x = fmaxf(v1.x, 0.f); v1.y = fmaxf(v1.y, 0.f);
            }
            *(float2*)(Crow + (size_t)r * NCOLS + col)       = v0;
            *(float2*)(Crow + (size_t)(r + 8) * NCOLS + col) = v1;
        }
    }
}

extern "C" void kernel_launch(void* const* d_in, const int* in_sizes, int n_in,
                              void* d_out, int out_size) {
    (void)in_sizes; (void)n_in; (void)out_size;
    const float* xs = (const float*)d_in[0];
    const float* w1 = (const float*)d_in[2];
    const float* b1 = (const float*)d_in[3];
    const float* w2 = (const float*)d_in[4];
    const float* b2 = (const float*)d_in[5];
    float* out = (float*)d_out;

    void* hptr = nullptr;
    cudaGetSymbolAddress(&hptr, g_hidden);
    float* hid = (float*)hptr;

    cudaFuncSetAttribute(ffn_mma<4096, 1024, true>,
                         cudaFuncAttributeMaxDynamicSharedMemorySize, SMEM_TOTAL);
    cudaFuncSetAttribute(ffn_mma<1024, 4096, false>,
                         cudaFuncAttributeMaxDynamicSharedMemorySize, SMEM_TOTAL);

    // GEMM1: [E] x (1024 x 4096 x 1024), bias+relu -> hidden (fp32)
    ffn_mma<4096, 1024, true><<<dim3(32, 8, 16), 256, SMEM_TOTAL>>>(xs, w1, b1, hid);
    // GEMM2: [E] x (1024 x 1024 x 4096), bias -> out
    ffn_mma<1024, 4096, false><<<dim3(8, 8, 16), 256, SMEM_TOTAL>>>(hid, w2, b2, out);
}

// round 4
// speedup vs baseline: 2.7110x; 1.0007x over previous
#include <cuda_runtime.h>
#include <cuda_bf16.h>
#include <cstdint>
#include <cstddef>

// E=16, D=1024, H=4096, N=16384 (1024 tokens/expert, contiguous).
// GEMM1: per-expert [1024 x 4096 x 1024], C = relu(X*W1^T + b1) -> hidden (bf16 hi/lo)
// GEMM2: per-expert [1024 x 1024 x 4096], Y = H*W2^T + b2       -> fp32 out
// All operands pre-split to bf16 hi/lo planes; 3-pass Ootomo mma.sync m16n8k16.
// Mainloop: cp.async (3-stage ring) -> ldmatrix -> HMMA. No fp32 anywhere hot.

static __device__ __nv_bfloat16 g_xs_h[16777216], g_xs_l[16777216];
static __device__ __nv_bfloat16 g_w1_h[67108864], g_w1_l[67108864];
static __device__ __nv_bfloat16 g_w2_h[67108864], g_w2_l[67108864];
static __device__ __nv_bfloat16 g_hid_h[67108864], g_hid_l[67108864];

__device__ __forceinline__ uint32_t smem_u32(const void* p) {
    uint32_t a;
    asm("{ .reg .u64 t; cvta.to.shared.u64 t, %1; cvt.u32.u64 %0, t; }"
        : "=r"(a) : "l"(p));
    return a;
}
#define SW128(x) ((x) ^ (((x) >> 3) & 0x70))

// lower half = bf16(a), upper half = bf16(b)
__device__ __forceinline__ uint32_t pack_bf2(float a, float b) {
    uint32_t r;
    asm("cvt.rn.bf16x2.f32 %0, %1, %2;" : "=r"(r) : "f"(b), "f"(a));
    return r;
}
__device__ __forceinline__ void ldsm4(uint32_t* r, uint32_t addr) {
    asm volatile("ldmatrix.sync.aligned.m8n8.x4.shared.b16 {%0,%1,%2,%3}, [%4];"
                 : "=r"(r[0]), "=r"(r[1]), "=r"(r[2]), "=r"(r[3]) : "r"(addr));
}
__device__ __forceinline__ void mma16816(float* c, const uint32_t* a,
                                         uint32_t b0, uint32_t b1) {
    asm volatile(
        "mma.sync.aligned.m16n8k16.row.col.f32.bf16.bf16.f32 "
        "{%0,%1,%2,%3}, {%4,%5,%6,%7}, {%8,%9}, {%0,%1,%2,%3};"
        : "+f"(c[0]), "+f"(c[1]), "+f"(c[2]), "+f"(c[3])
        : "r"(a[0]), "r"(a[1]), "r"(a[2]), "r"(a[3]), "r"(b0), "r"(b1));
}
__device__ __forceinline__ void cp16(uint32_t dst, const void* src) {
    asm volatile("cp.async.cg.shared.global [%0], [%1], 16;"
                 :: "r"(dst), "l"(src) : "memory");
}
#define CP_COMMIT() asm volatile("cp.async.commit_group;" ::: "memory")
#define CP_WAIT2()  asm volatile("cp.async.wait_group 2;" ::: "memory")

// -------- elementwise fp32 -> bf16 hi/lo planes --------
__global__ __launch_bounds__(256)
void split_f32_k(const float4* __restrict__ in, uint2* __restrict__ hi,
                 uint2* __restrict__ lo, int n4) {
    int i = blockIdx.x * 256 + threadIdx.x;
    if (i >= n4) return;
    float4 f = in[i];
    uint32_t h0 = pack_bf2(f.x, f.y), h1 = pack_bf2(f.z, f.w);
    float e0 = __uint_as_float(h0 << 16), e1 = __uint_as_float(h0 & 0xFFFF0000u);
    float e2 = __uint_as_float(h1 << 16), e3 = __uint_as_float(h1 & 0xFFFF0000u);
    uint32_t l0 = pack_bf2(f.x - e0, f.y - e1);
    uint32_t l1 = pack_bf2(f.z - e2, f.w - e3);
    hi[i] = make_uint2(h0, h1);
    lo[i] = make_uint2(l0, l1);
}

// SMEM stage (bf16, 64-elem rows = 128B, SW128 swizzled):
//   Ahi @0 (16KB)  Alo @16384  Bhi @32768  Blo @49152   -> 64KB/stage, 3 stages
static constexpr int STAGE = 65536;
static constexpr int SMEM_TOTAL = 3 * STAGE;  // 192 KB

template <int NCOLS, int KDIM, bool RELU, bool SPLIT>
__global__ __launch_bounds__(256, 1)
void ffn_mma2(const __nv_bfloat16* __restrict__ Ah, const __nv_bfloat16* __restrict__ Al,
              const __nv_bfloat16* __restrict__ Bh, const __nv_bfloat16* __restrict__ Bl,
              const float* __restrict__ bias,
              float* __restrict__ Cf,
              __nv_bfloat16* __restrict__ Ch, __nv_bfloat16* __restrict__ Cl)
{
    constexpr int NK = KDIM / 64;
    extern __shared__ char smem[];
    const uint32_t smb = smem_u32(smem);

    const int tid  = threadIdx.x;
    const int lane = tid & 31, warp = tid >> 5;
    const int wm = warp >> 2, wn = warp & 3;  // warp tile 64(M) x 32(N)
    const int e  = blockIdx.z;
    const int m0 = blockIdx.y * 128, n0 = blockIdx.x * 128;

    const __nv_bfloat16* Abh = Ah + ((size_t)e * 1024 + m0) * KDIM;
    const __nv_bfloat16* Abl = Al + ((size_t)e * 1024 + m0) * KDIM;
    const __nv_bfloat16* Bbh = Bh + ((size_t)e * NCOLS + n0) * KDIM;
    const __nv_bfloat16* Bbl = Bl + ((size_t)e * NCOLS + n0) * KDIM;

    // staging geometry: chunk s = tid + t*256; row = s>>3 (0..127), c = s&7
    int rows[4], sws[4];
    size_t goff[4];
#pragma unroll
    for (int t = 0; t < 4; t++) {
        int s = tid + (t << 8);
        rows[t] = s >> 3;
        int c = s & 7;
        sws[t]  = SW128(rows[t] * 128 + c * 16);
        goff[t] = (size_t)rows[t] * KDIM + c * 8;
    }

    // ldmatrix per-thread base offsets (validated in R3)
    const int xmask = (lane & 7) << 4;
    const int a_b0 = (wm * 64 + (lane & 15)) * 128 + ((lane >> 4) & 1) * 16;
    const int b_b0 = (wn * 32 + (lane & 7) + ((lane >> 4) & 1) * 8) * 128 +
                     ((lane >> 3) & 1) * 16;

    float acc[4][4][4];
#pragma unroll
    for (int i = 0; i < 4; i++)
#pragma unroll
        for (int j = 0; j < 4; j++)
#pragma unroll
            for (int q = 0; q < 4; q++) acc[i][j][q] = 0.f;

    auto stage = [&](int kt, uint32_t base) {
        const int kofs = kt * 64;
#pragma unroll
        for (int t = 0; t < 4; t++) {
            const size_t g = goff[t] + kofs;
            cp16(base + sws[t],          Abh + g);
            cp16(base + 16384 + sws[t],  Abl + g);
            cp16(base + 32768 + sws[t],  Bbh + g);
            cp16(base + 49152 + sws[t],  Bbl + g);
        }
    };

    // ---- prologue: fill 3 stages ----
    stage(0, smb);             CP_COMMIT();
    stage(1, smb + STAGE);     CP_COMMIT();
    stage(2, smb + 2 * STAGE); CP_COMMIT();
    CP_WAIT2();
    __syncthreads();

    int buf = 0;
    for (int kt = 0; kt < NK; ++kt) {
        const uint32_t sA = smb + buf * STAGE;
#pragma unroll
        for (int k16 = 0; k16 < 4; k16++) {
            uint32_t ah[4][4], al[4][4], bh[2][4], bl[2][4];
#pragma unroll
            for (int mt = 0; mt < 4; mt++) {
                int off = (a_b0 + mt * 2048 + k16 * 32) ^ xmask;
                ldsm4(ah[mt], sA + off);
                ldsm4(al[mt], sA + 16384 + off);
            }
#pragma unroll
            for (int nt2 = 0; nt2 < 2; nt2++) {
                int off = (b_b0 + nt2 * 2048 + k16 * 32) ^ xmask;
                ldsm4(bh[nt2], sA + 32768 + off);
                ldsm4(bl[nt2], sA + 49152 + off);
            }
#pragma unroll
            for (int mt = 0; mt < 4; mt++)
#pragma unroll
                for (int nt = 0; nt < 4; nt++) {
                    const int g = nt >> 1, s2 = (nt & 1) * 2;
                    mma16816(acc[mt][nt], ah[mt], bh[g][s2], bh[g][s2 + 1]);
                    mma16816(acc[mt][nt], ah[mt], bl[g][s2], bl[g][s2 + 1]);
                    mma16816(acc[mt][nt], al[mt], bh[g][s2], bh[g][s2 + 1]);
                }
        }

        __syncthreads();  // all warps done reading buf
        if (kt + 3 < NK) stage(kt + 3, sA);
        CP_COMMIT();      // keep group accounting uniform (empty groups ok)
        if (kt + 1 < NK) {
            CP_WAIT2();   // stage kt+1 landed
            __syncthreads();
        }
        buf = (buf == 2) ? 0 : buf + 1;
    }

    // ---- epilogue ----
    const float* bp = bias + (size_t)e * NCOLS + n0 + wn * 32;
    float2 bvv[4];
#pragma unroll
    for (int nt = 0; nt < 4; nt++)
        bvv[nt] = *(const float2*)(bp + nt * 8 + (lane & 3) * 2);

    const size_t rbase = (size_t)e * 1024 + m0 + wm * 64;
#pragma unroll
    for (int mt = 0; mt < 4; mt++) {
        int r = mt * 16 + (lane >> 2);
#pragma unroll
        for (int nt = 0; nt < 4; nt++) {
            int col = n0 + wn * 32 + nt * 8 + (lane & 3) * 2;
            float2 v0, v1;
            v0.x = acc[mt][nt][0] + bvv[nt].x;
            v0.y = acc[mt][nt][1] + bvv[nt].y;
            v1.x = acc[mt][nt][2] + bvv[nt].x;
            v1.y = acc[mt][nt][3] + bvv[nt].y;
            if (RELU) {
                v0.x = fmaxf(v0.x, 0.f); v0.y = fmaxf(v0.y, 0.f);
                v1.x = fmaxf(v1.x, 0.f); v1.y = fmaxf(v1.y, 0.f);
            }
            const size_t i0 = (rbase + r) * NCOLS + col;
            const size_t i1 = (rbase + r + 8) * NCOLS + col;
            if (SPLIT) {
                uint32_t h0 = pack_bf2(v0.x, v0.y);
                float e0 = __uint_as_float(h0 << 16), e1 = __uint_as_float(h0 & 0xFFFF0000u);
                uint32_t l0 = pack_bf2(v0.x - e0, v0.y - e1);
                uint32_t h1 = pack_bf2(v1.x, v1.y);
                float e2 = __uint_as_float(h1 << 16), e3 = __uint_as_float(h1 & 0xFFFF0000u);
                uint32_t l1 = pack_bf2(v1.x - e2, v1.y - e3);
                *(uint32_t*)(Ch + i0) = h0;
                *(uint32_t*)(Cl + i0) = l0;
                *(uint32_t*)(Ch + i1) = h1;
                *(uint32_t*)(Cl + i1) = l1;
            } else {
                *(float2*)(Cf + i0) = v0;
                *(float2*)(Cf + i1) = v1;
            }
        }
    }
}

extern "C" void kernel_launch(void* const* d_in, const int* in_sizes, int n_in,
                              void* d_out, int out_size) {
    (void)in_sizes; (void)n_in; (void)out_size;
    const float* xs = (const float*)d_in[0];
    const float* w1 = (const float*)d_in[2];
    const float* b1 = (const float*)d_in[3];
    const float* w2 = (const float*)d_in[4];
    const float* b2 = (const float*)d_in[5];
    float* out = (float*)d_out;

    void *xh, *xl, *w1h, *w1l, *w2h, *w2l, *hh, *hl;
    cudaGetSymbolAddress(&xh,  g_xs_h);  cudaGetSymbolAddress(&xl,  g_xs_l);
    cudaGetSymbolAddress(&w1h, g_w1_h);  cudaGetSymbolAddress(&w1l, g_w1_l);
    cudaGetSymbolAddress(&w2h, g_w2_h);  cudaGetSymbolAddress(&w2l, g_w2_l);
    cudaGetSymbolAddress(&hh,  g_hid_h); cudaGetSymbolAddress(&hl,  g_hid_l);

    cudaFuncSetAttribute(ffn_mma2<4096, 1024, true, true>,
                         cudaFuncAttributeMaxDynamicSharedMemorySize, SMEM_TOTAL);
    cudaFuncSetAttribute(ffn_mma2<1024, 4096, false, false>,
                         cudaFuncAttributeMaxDynamicSharedMemorySize, SMEM_TOTAL);

    // Pre-split operands to bf16 hi/lo planes
    split_f32_k<<<16384, 256>>>((const float4*)xs, (uint2*)xh, (uint2*)xl, 16777216 / 4);
    split_f32_k<<<65536, 256>>>((const float4*)w1, (uint2*)w1h, (uint2*)w1l, 67108864 / 4);
    split_f32_k<<<65536, 256>>>((const float4*)w2, (uint2*)w2h, (uint2*)w2l, 67108864 / 4);

    // GEMM1: bias+relu, split-output hidden planes
    ffn_mma2<4096, 1024, true, true><<<dim3(32, 8, 16), 256, SMEM_TOTAL>>>(
        (const __nv_bfloat16*)xh, (const __nv_bfloat16*)xl,
        (const __nv_bfloat16*)w1h, (const __nv_bfloat16*)w1l,
        b1, nullptr, (__nv_bfloat16*)hh, (__nv_bfloat16*)hl);
    // GEMM2: bias, fp32 out
    ffn_mma2<1024, 4096, false, false><<<dim3(8, 8, 16), 256, SMEM_TOTAL>>>(
        (const __nv_bfloat16*)hh, (const __nv_bfloat16*)hl,
        (const __nv_bfloat16*)w2h, (const __nv_bfloat16*)w2l,
        b2, out, nullptr, nullptr);
}